// round 16
// baseline (speedup 1.0000x reference)
#include <cuda_runtime.h>

// Problem constants
#define BP   128          // B*P
#define SEQ  1024         // S
#define DIM  1024         // D
#define NH   16           // heads
#define DH   64           // depth per head
#define SCALE 0.125f      // 1/sqrt(64)
#define SIGMA 0.1f

// ---------------- scratch (device globals; no allocation allowed) ------------
__device__ float g_qp[BP * DIM];
__device__ float g_kp[BP * DIM];
__device__ float g_vp[BP * DIM];
__device__ float g_part[32 * BP * DIM];    // per-s-chunk partial sums of attn·V
__device__ float g_zh[BP * DIM];           // merged attention output (mean_z)
__device__ float g_p3[12][BP * DIM];       // q/k/v GEMM k-split partials (4 each)
__device__ float g_pz[8][BP * DIM];        // z GEMM k-split partials
__device__ int   g_cnt3[3 * 32];           // last-block counters (zero-init)
__device__ int   g_cntZ[32];

// ---------------- partial projection GEMM (k-ranged, 4x4 micro-tile) --------
// partial[m][n] = sum_{k in [kBase, kBase+kLen)} x[m][k] * W[k][n]
// Block: 128 rows x 32 cols, 256 threads, micro-tile 4x4.
__device__ __forceinline__ void proj_partial_body(const float* __restrict__ x,
                                                  const float* __restrict__ W,
                                                  float* __restrict__ partial,
                                                  int colBase, int kBase, int kLen)
{
    __shared__ float xs[32][132];   // [k][m], padded
    __shared__ float ws[32][36];    // [k][n], padded

    const int tid = threadIdx.x;          // 0..255
    const int tx  = tid & 7;              // 8 col-groups of 4
    const int ty  = tid >> 3;             // 32 row-groups of 4

    float acc[4][4];
#pragma unroll
    for (int i = 0; i < 4; i++)
#pragma unroll
        for (int j = 0; j < 4; j++) acc[i][j] = 0.f;

    for (int kk = kBase; kk < kBase + kLen; kk += 32) {
#pragma unroll
        for (int r = 0; r < 4; r++) {
            int i  = tid + r * 256;
            int m  = i >> 3;
            int kq = (i & 7) << 2;
            float4 v = *reinterpret_cast<const float4*>(x + m * DIM + kk + kq);
            xs[kq + 0][m] = v.x;
            xs[kq + 1][m] = v.y;
            xs[kq + 2][m] = v.z;
            xs[kq + 3][m] = v.w;
        }
        {
            int k  = tid >> 3;
            int nq = (tid & 7) << 2;
            *reinterpret_cast<float4*>(&ws[k][nq]) =
                *reinterpret_cast<const float4*>(W + (kk + k) * DIM + colBase + nq);
        }
        __syncthreads();

#pragma unroll 8
        for (int k = 0; k < 32; k++) {
            float4 a = *reinterpret_cast<const float4*>(&xs[k][ty << 2]);
            float4 b = *reinterpret_cast<const float4*>(&ws[k][tx << 2]);
            acc[0][0] += a.x * b.x; acc[0][1] += a.x * b.y;
            acc[0][2] += a.x * b.z; acc[0][3] += a.x * b.w;
            acc[1][0] += a.y * b.x; acc[1][1] += a.y * b.y;
            acc[1][2] += a.y * b.z; acc[1][3] += a.y * b.w;
            acc[2][0] += a.z * b.x; acc[2][1] += a.z * b.y;
            acc[2][2] += a.z * b.z; acc[2][3] += a.z * b.w;
            acc[3][0] += a.w * b.x; acc[3][1] += a.w * b.y;
            acc[3][2] += a.w * b.z; acc[3][3] += a.w * b.w;
        }
        __syncthreads();
    }

    int n0 = colBase + (tx << 2);
#pragma unroll
    for (int i = 0; i < 4; i++) {
        int m = (ty << 2) + i;
        float4 r;
        r.x = acc[i][0]; r.y = acc[i][1]; r.z = acc[i][2]; r.w = acc[i][3];
        *reinterpret_cast<float4*>(partial + m * DIM + n0) = r;
    }
}

// last-block election: returns true for exactly one block per counter.
__device__ __forceinline__ bool last_block_elect(int* cnt, int arrivals)
{
    __shared__ int isLast;
    __threadfence();
    __syncthreads();
    if (threadIdx.x == 0) {
        int old = atomicAdd(cnt, 1);
        isLast = (old == arrivals - 1) ? 1 : 0;
        if (isLast) *cnt = 0;                 // reset for next graph replay
    }
    __syncthreads();
    if (!isLast) return false;
    __threadfence();                           // acquire: see peers' partials
    return true;
}

// proj3: grid (32 col-tiles, 3 matrices, 4 k-quarters); last block per
// (mat, col-tile) folds the 4 partials + bias + sigma*noise into the output.
__global__ void __launch_bounds__(256)
proj3_kernel(const float* __restrict__ q, const float* __restrict__ k,
             const float* __restrict__ v,
             const float* __restrict__ Wq, const float* __restrict__ Wk,
             const float* __restrict__ Wv,
             const float* __restrict__ bq, const float* __restrict__ bk,
             const float* __restrict__ bv,
             const float* __restrict__ nq, const float* __restrict__ nk,
             const float* __restrict__ nv)
{
    const int mat = blockIdx.y;
    const int kq  = blockIdx.z;
    const int colBase = blockIdx.x * 32;
    const float* x = (mat == 0) ? q  : (mat == 1) ? k  : v;
    const float* W = (mat == 0) ? Wq : (mat == 1) ? Wk : Wv;
    proj_partial_body(x, W, g_p3[mat * 4 + kq], colBase, kq * 256, 256);

    if (!last_block_elect(&g_cnt3[mat * 32 + blockIdx.x], 4)) return;

    const float* b = (mat == 0) ? bq : (mat == 1) ? bk : bv;
    const float* n = (mat == 0) ? nq : (mat == 1) ? nk : nv;
    float* o       = (mat == 0) ? g_qp : (mat == 1) ? g_kp : g_vp;
    const float* p0 = g_p3[mat * 4 + 0];
    const float* p1 = g_p3[mat * 4 + 1];
    const float* p2 = g_p3[mat * 4 + 2];
    const float* p3 = g_p3[mat * 4 + 3];

#pragma unroll
    for (int r = 0; r < 4; r++) {
        int i   = threadIdx.x + r * 256;       // 0..1023 = 128 rows x 8 grps
        int row = i >> 3;
        int n0  = colBase + ((i & 7) << 2);
        size_t idx = (size_t)row * DIM + n0;
        float4 a0 = *reinterpret_cast<const float4*>(p0 + idx);
        float4 a1 = *reinterpret_cast<const float4*>(p1 + idx);
        float4 a2 = *reinterpret_cast<const float4*>(p2 + idx);
        float4 a3 = *reinterpret_cast<const float4*>(p3 + idx);
        float4 bb = *reinterpret_cast<const float4*>(b + n0);
        float4 nn = *reinterpret_cast<const float4*>(n + idx);
        float4 rr;
        rr.x = ((a0.x + a1.x) + (a2.x + a3.x)) + bb.x + SIGMA * nn.x;
        rr.y = ((a0.y + a1.y) + (a2.y + a3.y)) + bb.y + SIGMA * nn.y;
        rr.z = ((a0.z + a1.z) + (a2.z + a3.z)) + bb.z + SIGMA * nn.z;
        rr.w = ((a0.w + a1.w) + (a2.w + a3.w)) + bb.w + SIGMA * nn.w;
        *reinterpret_cast<float4*>(o + idx) = rr;
    }
}

// projZ: grid (32 col-tiles, 1, 8 k-eighths); last block per col-tile folds
// the 8 partials + bias + sigma*noise directly into z_out.
__global__ void __launch_bounds__(256)
projZ_kernel(const float* __restrict__ Wz, const float* __restrict__ bz,
             const float* __restrict__ nz, float* __restrict__ z_out)
{
    const int kq = blockIdx.z;
    const int colBase = blockIdx.x * 32;
    proj_partial_body(g_zh, Wz, g_pz[kq], colBase, kq * 128, 128);

    if (!last_block_elect(&g_cntZ[blockIdx.x], 8)) return;

#pragma unroll
    for (int r = 0; r < 4; r++) {
        int i   = threadIdx.x + r * 256;
        int row = i >> 3;
        int n0  = colBase + ((i & 7) << 2);
        size_t idx = (size_t)row * DIM + n0;
        float4 s = make_float4(0.f, 0.f, 0.f, 0.f);
#pragma unroll
        for (int c = 0; c < 8; c++) {
            float4 p = *reinterpret_cast<const float4*>(g_pz[c] + idx);
            s.x += p.x; s.y += p.y; s.z += p.z; s.w += p.w;
        }
        float4 bb = *reinterpret_cast<const float4*>(bz + n0);
        float4 nn = *reinterpret_cast<const float4*>(nz + idx);
        float4 rr;
        rr.x = s.x + bb.x + SIGMA * nn.x;
        rr.y = s.y + bb.y + SIGMA * nn.y;
        rr.z = s.z + bb.z + SIGMA * nn.z;
        rr.w = s.w + bb.w + SIGMA * nn.w;
        *reinterpret_cast<float4*>(z_out + idx) = rr;
    }
}

// ---------------- copy K -> K_out (with slot write) + logits ----------------
// (R1/R5/R12 form — verbatim: 82% DRAM measured; zero added work)
__global__ void __launch_bounds__(256)
copyK_kernel(const float* __restrict__ K, float* __restrict__ Kout,
             float* __restrict__ logits, const int* __restrict__ tptr)
{
    const int bp  = blockIdx.y;
    const int s0  = blockIdx.x * 32;
    const int tid = threadIdx.x;
    const int t   = *tptr;

    __shared__ float pds[32][256];   // per-s, per-thread partial dot

    float4 q4 = *reinterpret_cast<const float4*>(g_qp + bp * DIM + (tid << 2));
    const float* kprow = g_kp + bp * DIM;
    const float* Kb = K    + (size_t)bp * SEQ * DIM;
    float*       Ob = Kout + (size_t)bp * SEQ * DIM;

#pragma unroll 4
    for (int sl = 0; sl < 32; sl++) {
        int s = s0 + sl;
        const float* src = (s == t) ? kprow : (Kb + (size_t)s * DIM);
        float4 v = *reinterpret_cast<const float4*>(src + (tid << 2));
        *reinterpret_cast<float4*>(Ob + (size_t)s * DIM + (tid << 2)) = v;
        pds[sl][tid] = v.x * q4.x + v.y * q4.y + v.z * q4.z + v.w * q4.w;
    }
    __syncthreads();

    for (int i = tid; i < 512; i += 256) {
        int h  = i & 15;
        int sl = i >> 4;
        float sum = 0.f;
#pragma unroll
        for (int j = 0; j < 16; j++) sum += pds[sl][(h << 4) + j];
        logits[((size_t)(bp * NH + h)) * SEQ + s0 + sl] = sum * SCALE;
    }
}

// ---------------- softmax in place: one block per row (single LDG round) ----
__global__ void __launch_bounds__(256)
softmax_kernel(float* __restrict__ attn)
{
    const int row  = blockIdx.x;                 // 2048 rows
    const int tid  = threadIdx.x;
    const int lane = tid & 31;
    const int wid  = tid >> 5;
    float* p = attn + (size_t)row * SEQ;

    __shared__ float red[8];

    float4 v = *reinterpret_cast<const float4*>(p + (tid << 2));

    float m = fmaxf(fmaxf(v.x, v.y), fmaxf(v.z, v.w));
#pragma unroll
    for (int o = 16; o > 0; o >>= 1) m = fmaxf(m, __shfl_xor_sync(0xffffffffu, m, o));
    if (lane == 0) red[wid] = m;
    __syncthreads();
    if (wid == 0) {
        float t = red[lane & 7];
#pragma unroll
        for (int o = 4; o > 0; o >>= 1) t = fmaxf(t, __shfl_xor_sync(0xffffffffu, t, o));
        red[lane & 7] = t;
    }
    __syncthreads();
    m = red[0];

    v.x = __expf(v.x - m); v.y = __expf(v.y - m);
    v.z = __expf(v.z - m); v.w = __expf(v.w - m);
    float s = (v.x + v.y) + (v.z + v.w);
#pragma unroll
    for (int o = 16; o > 0; o >>= 1) s += __shfl_xor_sync(0xffffffffu, s, o);
    if (lane == 0) red[wid] = s;
    __syncthreads();
    if (wid == 0) {
        float t = red[lane & 7];
#pragma unroll
        for (int o = 4; o > 0; o >>= 1) t += __shfl_xor_sync(0xffffffffu, t, o);
        red[lane & 7] = t;
    }
    __syncthreads();
    float inv = 1.f / red[0];

    v.x *= inv; v.y *= inv; v.z *= inv; v.w *= inv;
    *reinterpret_cast<float4*>(p + (tid << 2)) = v;
}

// ---------------- copy V -> V_out (slot write) + attn-weighted partials -----
// (R1/R5/R12 form — verbatim; zero added work)
__global__ void __launch_bounds__(256)
copyV_kernel(const float* __restrict__ V, float* __restrict__ Vout,
             const float* __restrict__ attn, const int* __restrict__ tptr)
{
    const int bp  = blockIdx.y;
    const int s0  = blockIdx.x * 32;
    const int tid = threadIdx.x;
    const int t   = *tptr;

    __shared__ float as[NH][32];
    for (int i = tid; i < NH * 32; i += 256) {
        int h  = i >> 5;
        int sl = i & 31;
        as[h][sl] = attn[((size_t)(bp * NH + h)) * SEQ + s0 + sl];
    }
    __syncthreads();

    const float* vprow = g_vp + bp * DIM;
    const float* Vb = V    + (size_t)bp * SEQ * DIM;
    float*       Ob = Vout + (size_t)bp * SEQ * DIM;

    const int h = tid >> 4;   // head of cols 4t..4t+3
    float4 acc = make_float4(0.f, 0.f, 0.f, 0.f);

#pragma unroll 4
    for (int sl = 0; sl < 32; sl++) {
        int s = s0 + sl;
        const float* src = (s == t) ? vprow : (Vb + (size_t)s * DIM);
        float4 v = *reinterpret_cast<const float4*>(src + (tid << 2));
        *reinterpret_cast<float4*>(Ob + (size_t)s * DIM + (tid << 2)) = v;
        float a = as[h][sl];
        acc.x += a * v.x; acc.y += a * v.y; acc.z += a * v.z; acc.w += a * v.w;
    }
    *reinterpret_cast<float4*>(g_part + ((size_t)blockIdx.x * BP + bp) * DIM + (tid << 2)) = acc;
}

// ---------------- reduce the 32 s-chunk partials into g_zh (float4) ---------
__global__ void __launch_bounds__(256)
reduce_kernel()
{
    int i = (blockIdx.x * 256 + threadIdx.x) << 2;   // 128 blocks over BP*DIM
    float4 s = make_float4(0.f, 0.f, 0.f, 0.f);
#pragma unroll
    for (int c = 0; c < 32; c++) {
        float4 p = *reinterpret_cast<const float4*>(&g_part[(size_t)c * (BP * DIM) + i]);
        s.x += p.x; s.y += p.y; s.z += p.z; s.w += p.w;
    }
    *reinterpret_cast<float4*>(&g_zh[i]) = s;
}

// ---------------- launch ----------------------------------------------------
extern "C" void kernel_launch(void* const* d_in, const int* in_sizes, int n_in,
                              void* d_out, int out_size)
{
    const float* q   = (const float*)d_in[0];
    const float* k   = (const float*)d_in[1];
    const float* v   = (const float*)d_in[2];
    const float* Kin = (const float*)d_in[3];
    const float* Vin = (const float*)d_in[4];
    const float* Wq  = (const float*)d_in[5];
    const float* bq  = (const float*)d_in[6];
    const float* Wk  = (const float*)d_in[7];
    const float* bk  = (const float*)d_in[8];
    const float* Wv  = (const float*)d_in[9];
    const float* bv  = (const float*)d_in[10];
    const float* Wz  = (const float*)d_in[11];
    const float* bz  = (const float*)d_in[12];
    const float* nq  = (const float*)d_in[13];
    const float* nk  = (const float*)d_in[14];
    const float* nv  = (const float*)d_in[15];
    const float* nz  = (const float*)d_in[16];
    const int* tstep = (const int*)d_in[17];

    float* out   = (float*)d_out;
    float* z_out = out;                                       // 128*1024
    float* K_out = out + (size_t)BP * DIM;                    // 128*1024*1024
    float* V_out = K_out + (size_t)BP * SEQ * DIM;
    float* attn  = V_out + (size_t)BP * SEQ * DIM;            // 128*16*1024

    // 1. q/k/v projections (k-split x4) with fused last-block combine
    proj3_kernel<<<dim3(32, 3, 4), 256>>>(q, k, v, Wq, Wk, Wv,
                                          bq, bk, bv, nq, nk, nv);
    // 2. K copy (slot write at t) fused with logits
    copyK_kernel<<<dim3(32, BP), 256>>>(Kin, K_out, attn, tstep);
    // 3. softmax in place (block per row)
    softmax_kernel<<<2048, 256>>>(attn);
    // 4. V copy (slot write at t) fused with attn-weighted partial sums
    copyV_kernel<<<dim3(32, BP), 256>>>(Vin, V_out, attn, tstep);
    // 5. reduce partials -> zh (float4)
    reduce_kernel<<<128, 256>>>();
    // 6. z projection (k-split x8) with fused last-block combine -> z_out
    projZ_kernel<<<dim3(32, 1, 8), 256>>>(Wz, bz, nz, z_out);
}